// round 13
// baseline (speedup 1.0000x reference)
#include <cuda_runtime.h>
#include <cuda_fp16.h>
#include <math.h>

#define D_MODEL 2048
#define NH 16
#define HD 128
#define SEQ 2048
#define BATCH 4
#define ROWS (BATCH * SEQ)       // 8192
#define D_FF 8192
#define QKV_N (3 * D_MODEL)      // 6144

// -------- scratch (static device globals; no cudaMalloc allowed) --------
__device__ __half g_h[(size_t)ROWS * D_MODEL];     // LN output (half)
__device__ __half g_qkv[(size_t)ROWS * QKV_N];     // fused QKV (half)
__device__ __half g_attn[(size_t)ROWS * D_MODEL];  // attention out (half)
__device__ __half g_mlp[(size_t)ROWS * D_FF];      // MLP hidden (half)
// half weights: Wqkv | Wo | W1 | W2
#define WQKV_OFF 0
#define WO_OFF   (3 * D_MODEL * D_MODEL)                 // 12582912
#define W1_OFF   (WO_OFF + D_MODEL * D_MODEL)            // 16777216
#define W2_OFF   (W1_OFF + D_FF * D_MODEL)               // 33554432
#define WR_TOTAL (W2_OFF + D_MODEL * D_FF)               // 50331648
__device__ __half g_wh[(size_t)WR_TOTAL];

// segment boundaries in units of 8 floats
#define N8_QKV (WO_OFF / 8)        // 1572864
#define N8_WO  (W1_OFF / 8)        // 2097152
#define N8_W1  (W2_OFF / 8)        // 4194304
#define N8_ALL (WR_TOTAL / 8)      // 6291456

// ============================ helpers ============================
__device__ __forceinline__ void mma_f16(float* c,
    unsigned a0, unsigned a1, unsigned a2, unsigned a3,
    unsigned b0, unsigned b1)
{
    asm volatile(
        "mma.sync.aligned.m16n8k16.row.col.f32.f16.f16.f32 "
        "{%0,%1,%2,%3}, {%4,%5,%6,%7}, {%8,%9}, {%0,%1,%2,%3};"
        : "+f"(c[0]), "+f"(c[1]), "+f"(c[2]), "+f"(c[3])
        : "r"(a0), "r"(a1), "r"(a2), "r"(a3), "r"(b0), "r"(b1));
}

__device__ __forceinline__ void ldsm4(unsigned* r, unsigned addr) {
    asm volatile(
        "ldmatrix.sync.aligned.m8n8.x4.shared.b16 {%0,%1,%2,%3}, [%4];"
        : "=r"(r[0]), "=r"(r[1]), "=r"(r[2]), "=r"(r[3]) : "r"(addr));
}
__device__ __forceinline__ void ldsm4t(unsigned* r, unsigned addr) {
    asm volatile(
        "ldmatrix.sync.aligned.m8n8.x4.trans.shared.b16 {%0,%1,%2,%3}, [%4];"
        : "=r"(r[0]), "=r"(r[1]), "=r"(r[2]), "=r"(r[3]) : "r"(addr));
}

__device__ __forceinline__ void cp16(void* dst_sh, const void* src) {
    unsigned sa = (unsigned)__cvta_generic_to_shared(dst_sh);
    asm volatile("cp.async.cg.shared.global [%0], [%1], 16;" :: "r"(sa), "l"(src));
}
__device__ __forceinline__ void cp_commit() {
    asm volatile("cp.async.commit_group;");
}
template <int N>
__device__ __forceinline__ void cp_wait() {
    asm volatile("cp.async.wait_group %0;" :: "n"(N));
}

__device__ __forceinline__ float gelu_exact(float v) {
    return 0.5f * v * (1.0f + erff(v * 0.70710678118654752f));
}

__device__ __forceinline__ unsigned h2u(__half2 h) {
    unsigned u;
    *(__half2*)&u = h;
    return u;
}

// ============================ fused fp32 -> fp16 weight convert ============================
__global__ void __launch_bounds__(256) to_half_all_kernel(
    const float4* __restrict__ s_qkv, const float4* __restrict__ s_wo,
    const float4* __restrict__ s_w1,  const float4* __restrict__ s_w2,
    uint4* __restrict__ dst)
{
    int i = blockIdx.x * 256 + threadIdx.x;
    if (i >= N8_ALL) return;
    const float4* src;
    int j;
    if (i < N8_QKV)      { src = s_qkv; j = i; }
    else if (i < N8_WO)  { src = s_wo;  j = i - N8_QKV; }
    else if (i < N8_W1)  { src = s_w1;  j = i - N8_WO; }
    else                 { src = s_w2;  j = i - N8_W1; }
    float4 v0 = src[2 * j], v1 = src[2 * j + 1];
    uint4 o;
    o.x = h2u(__floats2half2_rn(v0.x, v0.y));
    o.y = h2u(__floats2half2_rn(v0.z, v0.w));
    o.z = h2u(__floats2half2_rn(v1.x, v1.y));
    o.w = h2u(__floats2half2_rn(v1.z, v1.w));
    dst[i] = o;
}

// ============================ LayerNorm (half output) ============================
__global__ void __launch_bounds__(256) ln_kernel(
    const float* __restrict__ x, const float* __restrict__ g,
    const float* __restrict__ b, __half* __restrict__ out)
{
    __shared__ float red[2][8];
    int row = blockIdx.x, tid = threadIdx.x;
    const float4* xr = (const float4*)(x + (size_t)row * D_MODEL);
    float4 v0 = xr[tid];
    float4 v1 = xr[tid + 256];
    float s  = v0.x + v0.y + v0.z + v0.w + v1.x + v1.y + v1.z + v1.w;
    float s2 = v0.x*v0.x + v0.y*v0.y + v0.z*v0.z + v0.w*v0.w
             + v1.x*v1.x + v1.y*v1.y + v1.z*v1.z + v1.w*v1.w;
    #pragma unroll
    for (int o = 16; o; o >>= 1) {
        s  += __shfl_xor_sync(0xffffffffu, s,  o);
        s2 += __shfl_xor_sync(0xffffffffu, s2, o);
    }
    if ((tid & 31) == 0) { red[0][tid >> 5] = s; red[1][tid >> 5] = s2; }
    __syncthreads();
    if (tid < 32) {
        float a = (tid < 8) ? red[0][tid] : 0.f;
        float c = (tid < 8) ? red[1][tid] : 0.f;
        #pragma unroll
        for (int o = 4; o; o >>= 1) {
            a += __shfl_xor_sync(0xffffffffu, a, o);
            c += __shfl_xor_sync(0xffffffffu, c, o);
        }
        if (tid == 0) { red[0][0] = a; red[1][0] = c; }
    }
    __syncthreads();
    float mean = red[0][0] * (1.f / D_MODEL);
    float var  = red[1][0] * (1.f / D_MODEL) - mean * mean;
    float rstd = rsqrtf(var + 1e-5f);

    const float4* gr = (const float4*)g;
    const float4* br = (const float4*)b;
    __half2* orow = (__half2*)(out + (size_t)row * D_MODEL);
    #pragma unroll
    for (int p = 0; p < 2; p++) {
        float4 v = p ? v1 : v0;
        float4 gw = gr[tid + p * 256];
        float4 bw = br[tid + p * 256];
        orow[2 * (tid + p * 256) + 0] = __floats2half2_rn(
            (v.x - mean) * rstd * gw.x + bw.x,
            (v.y - mean) * rstd * gw.y + bw.y);
        orow[2 * (tid + p * 256) + 1] = __floats2half2_rn(
            (v.z - mean) * rstd * gw.z + bw.z,
            (v.w - mean) * rstd * gw.w + bw.w);
    }
}

// ============================ fp16 mma GEMM: cp.async 3-stage + ldmatrix ============================
// (round-11 proven config: 128x128xBK64, 256 threads, 2 CTAs/SM, single
//  barrier per ktile: wait<1> -> BAR -> prefetch(kb+2) -> compute(kb))
// EPI: 0 = bias -> half; 1 = bias + fp32 residual -> fp32; 2 = bias + GELU -> half
#define GBM 128
#define GBN 128
#define GBK 64
#define TILE_H (128 * 64)
#define NSTAGE 3
#define STAGE_H (2 * TILE_H)
#define GEMM_SMEM (NSTAGE * STAGE_H * 2)  // 98304 B

template <int EPI>
__global__ void __launch_bounds__(256, 2) gemm_kernel(
    const __half* __restrict__ A, const __half* __restrict__ B,
    const float* __restrict__ bias, const float* __restrict__ res,
    void* __restrict__ Cv, int M, int N, int K)
{
    extern __shared__ __half smh[];
    int tid = threadIdx.x;
    int bm = blockIdx.y, bn = blockIdx.x;
    int warp = tid >> 5, lane = tid & 31;
    int wm = warp >> 1, wn = warp & 1;
    int g = lane >> 2, c = lane & 3;

    int srow0 = tid >> 3, sc8 = tid & 7;
    const __half* Asrc0 = A + (size_t)(bm * GBM + srow0) * K + sc8 * 8;
    const __half* Bsrc0 = B + (size_t)(bn * GBN + srow0) * K + sc8 * 8;
    int sdst0 = srow0 * 64 + ((sc8 ^ (srow0 & 7)) << 3);

    float acc[2][8][4];
    #pragma unroll
    for (int mt = 0; mt < 2; mt++)
        #pragma unroll
        for (int nt = 0; nt < 8; nt++)
            #pragma unroll
            for (int q = 0; q < 4; q++) acc[mt][nt][q] = 0.f;

    int kt = K / GBK;

    unsigned smbase = (unsigned)__cvta_generic_to_shared(smh);
    int l7 = lane & 7;
    int arow = wm * 32 + l7 + ((lane >> 3) & 1) * 8;
    int brow = wn * 64 + l7 + (lane >> 4) * 8;
    unsigned abyte0 = smbase + arow * 128;
    unsigned bbyte0 = smbase + TILE_H * 2 + brow * 128;
    int kA = lane >> 4;
    int kB = (lane >> 3) & 1;

    // prologue: stage ktiles 0,1 (two commit groups)
    #pragma unroll
    for (int s = 0; s < NSTAGE - 1; s++) {
        #pragma unroll
        for (int p = 0; p < 4; p++) {
            cp16(smh + s * STAGE_H + sdst0 + p * 2048,
                 Asrc0 + (size_t)(32 * p) * K + s * GBK);
            cp16(smh + s * STAGE_H + TILE_H + sdst0 + p * 2048,
                 Bsrc0 + (size_t)(32 * p) * K + s * GBK);
        }
        cp_commit();
    }

    for (int kb = 0; kb < kt; ++kb) {
        int cur = kb % NSTAGE;
        if (kb < kt - 1) cp_wait<1>(); else cp_wait<0>();
        __syncthreads();   // publish stage kb; all warps done reading (kb+2)%3

        if (kb + 2 < kt) {
            int nst = (kb + 2) % NSTAGE;
            #pragma unroll
            for (int p = 0; p < 4; p++) {
                cp16(smh + nst * STAGE_H + sdst0 + p * 2048,
                     Asrc0 + (size_t)(32 * p) * K + (kb + 2) * GBK);
                cp16(smh + nst * STAGE_H + TILE_H + sdst0 + p * 2048,
                     Bsrc0 + (size_t)(32 * p) * K + (kb + 2) * GBK);
            }
            cp_commit();
        }

        unsigned aB = abyte0 + cur * (STAGE_H * 2);
        unsigned bB = bbyte0 + cur * (STAGE_H * 2);

        #pragma unroll
        for (int kc = 0; kc < 4; kc++) {
            unsigned fa[2][4];
            #pragma unroll
            for (int mt = 0; mt < 2; mt++)
                ldsm4(fa[mt], aB + mt * (16 * 128) + ((unsigned)((2 * kc + kA) ^ l7) << 4));
            unsigned fb[4][4];
            #pragma unroll
            for (int p = 0; p < 4; p++)
                ldsm4(fb[p], bB + p * (16 * 128) + ((unsigned)((2 * kc + kB) ^ l7) << 4));
            #pragma unroll
            for (int mt = 0; mt < 2; mt++)
                #pragma unroll
                for (int nt = 0; nt < 8; nt++)
                    mma_f16(acc[mt][nt],
                            fa[mt][0], fa[mt][1], fa[mt][2], fa[mt][3],
                            fb[nt >> 1][(nt & 1) * 2], fb[nt >> 1][(nt & 1) * 2 + 1]);
        }
    }

    int row0g = bm * GBM + wm * 32;
    int col0g = bn * GBN + wn * 64;
    #pragma unroll
    for (int mt = 0; mt < 2; mt++)
        #pragma unroll
        for (int nt = 0; nt < 8; nt++)
            #pragma unroll
            for (int h2 = 0; h2 < 2; h2++) {
                int row = row0g + mt * 16 + h2 * 8 + g;
                int col = col0g + nt * 8 + 2 * c;
                float vx = acc[mt][nt][2 * h2 + 0] + bias[col];
                float vy = acc[mt][nt][2 * h2 + 1] + bias[col + 1];
                size_t off = (size_t)row * N + col;
                if (EPI == 0) {
                    __half* Ch = (__half*)Cv;
                    *(__half2*)(Ch + off) = __floats2half2_rn(vx, vy);
                } else if (EPI == 2) {
                    __half* Ch = (__half*)Cv;
                    *(__half2*)(Ch + off) =
                        __floats2half2_rn(gelu_exact(vx), gelu_exact(vy));
                } else {
                    float* Cf = (float*)Cv;
                    float2 r = *(const float2*)(res + off);
                    vx += r.x; vy += r.y;
                    *(float2*)(Cf + off) = make_float2(vx, vy);
                }
            }
}

// ============================ fp16 tensor-core flash attention ============================
// (round-11 proven: double-buffered K/V, single barrier per tile, heavy-first)
#define QS_OFF 0                       // 2 t x 128x64 halfs (32 KB)
#define KS_OFF (2 * 128 * 64)          // 2 buf x 2 t x 64x64 (32 KB)
#define VS_OFF (KS_OFF + 2 * 2 * 64 * 64)
#define PS_OFF (VS_OFF + 2 * 2 * 64 * 64)  // 8 warps x 16x64 (16 KB)
#define ATT_HALFS (PS_OFF + 8 * 16 * 64)
#define ATT_SMEM (ATT_HALFS * 2)       // 114688 B
#define NEG_BIG (-1e30f)

__global__ void __launch_bounds__(256, 1) attn_kernel(
    const __half* __restrict__ qkv, const float* __restrict__ slopes,
    __half* __restrict__ out)
{
    extern __shared__ __half smA[];
    int qi = (int)gridDim.x - 1 - (int)blockIdx.x;   // heavy blocks first
    int h = blockIdx.y, b = blockIdx.z;
    int tid = threadIdx.x, warp = tid >> 5, lane = tid & 31;
    int g = lane >> 2, c = lane & 3, l7 = lane & 7;
    int q0 = qi * 128;
    float slope = slopes[h];
    const float scale = 0.08838834764831845f;   // 1/sqrt(128)

    const __half* qb = qkv + (size_t)(b * SEQ) * QKV_N + h * HD;
    const __half* kb = qb + D_MODEL;
    const __half* vb = qb + 2 * D_MODEL;

    unsigned smbase = (unsigned)__cvta_generic_to_shared(smA);
    __half* Pw = smA + PS_OFF + warp * 1024;
    unsigned pbase = smbase + (PS_OFF + warp * 1024) * 2;

    // stage Q (resident)
    for (int i = tid; i < 2048; i += 256) {
        int row = i >> 4, cc = i & 15;
        int t = cc >> 3, cw = cc & 7;
        cp16(smA + QS_OFF + t * 8192 + row * 64 + ((cw ^ (row & 7)) << 3),
             qb + (size_t)(q0 + row) * QKV_N + cc * 8);
    }
    cp_commit();

    // stage K/V tile 0 into buffer 0
    for (int i = tid; i < 1024; i += 256) {
        int row = i >> 4, cc = i & 15;
        int t = cc >> 3, cw = cc & 7;
        int d = row * 64 + ((cw ^ (row & 7)) << 3);
        cp16(smA + KS_OFF + t * 4096 + d, kb + (size_t)row * QKV_N + cc * 8);
        cp16(smA + VS_OFF + t * 4096 + d, vb + (size_t)row * QKV_N + cc * 8);
    }
    cp_commit();

    float m0 = NEG_BIG, m1 = NEG_BIG, l0 = 0.f, l1 = 0.f;
    float oc[16][4];
    #pragma unroll
    for (int nt = 0; nt < 16; nt++)
        #pragma unroll
        for (int q = 0; q < 4; q++) oc[nt][q] = 0.f;

    int rowA = 16 * warp + g;
    int qr0 = q0 + rowA, qr1 = qr0 + 8;

    int a_roff = ((lane >> 3) & 1) * 8 + l7;
    int a_csel = lane >> 4;
    int b_roff = (lane >> 4) * 8 + l7;
    int b_csel = (lane >> 3) & 1;
    int v_roff = ((lane >> 3) & 1) * 8 + l7;
    int v_csel = lane >> 4;

    int ntiles = 2 * qi + 2;
    for (int jt = 0; jt < ntiles; jt++) {
        int bsel = jt & 1;
        cp_wait<0>();
        __syncthreads();

        if (jt + 1 < ntiles) {
            int j1 = (jt + 1) * 64;
            int ns = bsel ^ 1;
            for (int i = tid; i < 1024; i += 256) {
                int row = i >> 4, cc = i & 15;
                int t = cc >> 3, cw = cc & 7;
                int d = row * 64 + ((cw ^ (row & 7)) << 3);
                cp16(smA + KS_OFF + ns * 8192 + t * 4096 + d,
                     kb + (size_t)(j1 + row) * QKV_N + cc * 8);
                cp16(smA + VS_OFF + ns * 8192 + t * 4096 + d,
                     vb + (size_t)(j1 + row) * QKV_N + cc * 8);
            }
            cp_commit();
        }

        int j0 = jt * 64;
        unsigned kbb = smbase + (KS_OFF + bsel * 8192) * 2;
        unsigned vbb = smbase + (VS_OFF + bsel * 8192) * 2;

        float sc[8][4];
        #pragma unroll
        for (int nt = 0; nt < 8; nt++)
            #pragma unroll
            for (int q = 0; q < 4; q++) sc[nt][q] = 0.f;

        #pragma unroll
        for (int kc = 0; kc < 8; kc++) {
            int t = kc >> 2, k2 = kc & 3;
            unsigned fa[4];
            {
                int row = warp * 16 + a_roff;
                unsigned addr = smbase +
                    (QS_OFF + t * 8192 + row * 64 + (((k2 * 2 + a_csel) ^ l7) << 3)) * 2;
                ldsm4(fa, addr);
            }
            unsigned fb[4][4];
            #pragma unroll
            for (int p = 0; p < 4; p++) {
                int key = 16 * p + b_roff;
                unsigned addr = kbb +
                    (t * 4096 + key * 64 + (((k2 * 2 + b_csel) ^ l7) << 3)) * 2;
                ldsm4(fb[p], addr);
            }
            #pragma unroll
            for (int nt = 0; nt < 8; nt++)
                mma_f16(sc[nt], fa[0], fa[1], fa[2], fa[3],
                        fb[nt >> 1][(nt & 1) * 2], fb[nt >> 1][(nt & 1) * 2 + 1]);
        }

        bool masked = (jt >= 2 * qi);
        float tm0 = NEG_BIG, tm1 = NEG_BIG;
        #pragma unroll
        for (int nt = 0; nt < 8; nt++) {
            #pragma unroll
            for (int j = 0; j < 2; j++) {
                int col = j0 + nt * 8 + 2 * c + j;
                float s0 = sc[nt][j]     * scale + slope * (float)(col - qr0);
                float s1 = sc[nt][2 + j] * scale + slope * (float)(col - qr1);
                if (masked) {
                    if (col > qr0) s0 = NEG_BIG;
                    if (col > qr1) s1 = NEG_BIG;
                }
                sc[nt][j] = s0; sc[nt][2 + j] = s1;
                tm0 = fmaxf(tm0, s0); tm1 = fmaxf(tm1, s1);
            }
        }
        #pragma unroll
        for (int o = 1; o < 4; o <<= 1) {
            tm0 = fmaxf(tm0, __shfl_xor_sync(0xffffffffu, tm0, o));
            tm1 = fmaxf(tm1, __shfl_xor_sync(0xffffffffu, tm1, o));
        }
        float mn0 = fmaxf(m0, tm0), mn1 = fmaxf(m1, tm1);
        float alpha0 = __expf(m0 - mn0), alpha1 = __expf(m1 - mn1);
        float rs0 = 0.f, rs1 = 0.f;
        #pragma unroll
        for (int nt = 0; nt < 8; nt++) {
            #pragma unroll
            for (int j = 0; j < 2; j++) {
                float p0 = __expf(sc[nt][j]     - mn0);
                float p1 = __expf(sc[nt][2 + j] - mn1);
                sc[nt][j] = p0; sc[nt][2 + j] = p1;
                rs0 += p0; rs1 += p1;
            }
        }
        #pragma unroll
        for (int o = 1; o < 4; o <<= 1) {
            rs0 += __shfl_xor_sync(0xffffffffu, rs0, o);
            rs1 += __shfl_xor_sync(0xffffffffu, rs1, o);
        }
        l0 = l0 * alpha0 + rs0;
        l1 = l1 * alpha1 + rs1;
        m0 = mn0; m1 = mn1;
        #pragma unroll
        for (int nt = 0; nt < 16; nt++) {
            oc[nt][0] *= alpha0; oc[nt][1] *= alpha0;
            oc[nt][2] *= alpha1; oc[nt][3] *= alpha1;
        }

        __syncwarp();
        #pragma unroll
        for (int nt = 0; nt < 8; nt++) {
            *(__half2*)(Pw + g * 64 + ((nt ^ (g & 7)) << 3) + 2 * c) =
                __floats2half2_rn(sc[nt][0], sc[nt][1]);
            *(__half2*)(Pw + (g + 8) * 64 + ((nt ^ (g & 7)) << 3) + 2 * c) =
                __floats2half2_rn(sc[nt][2], sc[nt][3]);
        }
        __syncwarp();

        #pragma unroll
        for (int kc2 = 0; kc2 < 4; kc2++) {
            unsigned fa[4];
            {
                unsigned addr = pbase +
                    (a_roff * 64 + (((kc2 * 2 + a_csel) ^ l7) << 3)) * 2;
                ldsm4(fa, addr);
            }
            unsigned fv[8][4];
            #pragma unroll
            for (int nv = 0; nv < 8; nv++) {
                int t = nv >> 2;
                int cw = (nv & 3) * 2 + v_csel;
                int key = kc2 * 16 + v_roff;
                unsigned addr = vbb +
                    (t * 4096 + key * 64 + ((cw ^ l7) << 3)) * 2;
                ldsm4t(fv[nv], addr);
            }
            #pragma unroll
            for (int nt = 0; nt < 16; nt++)
                mma_f16(oc[nt], fa[0], fa[1], fa[2], fa[3],
                        fv[nt >> 1][(nt & 1) * 2], fv[nt >> 1][(nt & 1) * 2 + 1]);
        }
    }

    float inv0 = 1.f / l0, inv1 = 1.f / l1;
    __half* ob  = out + (size_t)(b * SEQ + qr0) * D_MODEL + h * HD;
    __half* ob1 = ob + 8 * D_MODEL;
    #pragma unroll
    for (int nt = 0; nt < 16; nt++) {
        *(__half2*)&ob[nt * 8 + 2 * c] =
            __floats2half2_rn(oc[nt][0] * inv0, oc[nt][1] * inv0);
        *(__half2*)&ob1[nt * 8 + 2 * c] =
            __floats2half2_rn(oc[nt][2] * inv1, oc[nt][3] * inv1);
    }
}

// ============================ launch ============================
extern "C" void kernel_launch(void* const* d_in, const int* in_sizes, int n_in,
                              void* d_out, int out_size)
{
    const float* x      = (const float*)d_in[0];
    const float* ln1_w  = (const float*)d_in[1];
    const float* ln1_b  = (const float*)d_in[2];
    const float* Wqkv   = (const float*)d_in[3];
    const float* bqkv   = (const float*)d_in[4];
    const float* Wo     = (const float*)d_in[5];
    const float* bo     = (const float*)d_in[6];
    const float* ln2_w  = (const float*)d_in[7];
    const float* ln2_b  = (const float*)d_in[8];
    const float* W1     = (const float*)d_in[9];
    const float* b1     = (const float*)d_in[10];
    const float* W2     = (const float*)d_in[11];
    const float* b2     = (const float*)d_in[12];
    const float* slopes = (const float*)d_in[13];
    float* out = (float*)d_out;

    __half *h, *qkv, *attn, *mlp, *wh;
    cudaGetSymbolAddress((void**)&h,    g_h);
    cudaGetSymbolAddress((void**)&qkv,  g_qkv);
    cudaGetSymbolAddress((void**)&attn, g_attn);
    cudaGetSymbolAddress((void**)&mlp,  g_mlp);
    cudaGetSymbolAddress((void**)&wh,   g_wh);

    cudaFuncSetAttribute(attn_kernel,
                         cudaFuncAttributeMaxDynamicSharedMemorySize, ATT_SMEM);
    cudaFuncSetAttribute(gemm_kernel<0>,
                         cudaFuncAttributeMaxDynamicSharedMemorySize, GEMM_SMEM);
    cudaFuncSetAttribute(gemm_kernel<1>,
                         cudaFuncAttributeMaxDynamicSharedMemorySize, GEMM_SMEM);
    cudaFuncSetAttribute(gemm_kernel<2>,
                         cudaFuncAttributeMaxDynamicSharedMemorySize, GEMM_SMEM);

    // 0. convert all weights to half (single fused launch)
    to_half_all_kernel<<<(N8_ALL + 255) / 256, 256>>>(
        (const float4*)Wqkv, (const float4*)Wo,
        (const float4*)W1,   (const float4*)W2, (uint4*)wh);

    // 1. LN1 -> half
    ln_kernel<<<ROWS, 256>>>(x, ln1_w, ln1_b, h);
    // 2. QKV GEMM -> half
    gemm_kernel<0><<<dim3(QKV_N / GBN, ROWS / GBM), 256, GEMM_SMEM>>>(
        h, wh + WQKV_OFF, bqkv, nullptr, qkv, ROWS, QKV_N, D_MODEL);
    // 3. Flash attention with ALiBi (fp16 mma) -> half
    attn_kernel<<<dim3(SEQ / 128, NH, BATCH), 256, ATT_SMEM>>>(qkv, slopes, attn);
    // 4. O projection + residual (x) -> d_out fp32
    gemm_kernel<1><<<dim3(D_MODEL / GBN, ROWS / GBM), 256, GEMM_SMEM>>>(
        attn, wh + WO_OFF, bo, x, out, ROWS, D_MODEL, D_MODEL);
    // 5. LN2 -> half
    ln_kernel<<<ROWS, 256>>>(out, ln2_w, ln2_b, h);
    // 6. MLP up + GELU -> half
    gemm_kernel<2><<<dim3(D_FF / GBN, ROWS / GBM), 256, GEMM_SMEM>>>(
        h, wh + W1_OFF, b1, nullptr, mlp, ROWS, D_FF, D_MODEL);
    // 7. MLP down + residual (x1 in d_out) -> d_out fp32 final
    gemm_kernel<1><<<dim3(D_MODEL / GBN, ROWS / GBM), 256, GEMM_SMEM>>>(
        mlp, wh + W2_OFF, b2, out, out, ROWS, D_MODEL, D_FF);
}

// round 14
// speedup vs baseline: 1.5486x; 1.5486x over previous
#include <cuda_runtime.h>
#include <cuda_fp16.h>
#include <math.h>

#define D_MODEL 2048
#define NH 16
#define HD 128
#define SEQ 2048
#define BATCH 4
#define ROWS (BATCH * SEQ)       // 8192
#define D_FF 8192
#define QKV_N (3 * D_MODEL)      // 6144

// -------- scratch (static device globals; no cudaMalloc allowed) --------
__device__ __half g_h[(size_t)ROWS * D_MODEL];     // LN output (half)
__device__ __half g_qkv[(size_t)ROWS * QKV_N];     // fused QKV (half)
__device__ __half g_attn[(size_t)ROWS * D_MODEL];  // attention out (half)
__device__ __half g_mlp[(size_t)ROWS * D_FF];      // MLP hidden (half)
// half weights: Wqkv | Wo | W1 | W2
#define WQKV_OFF 0
#define WO_OFF   (3 * D_MODEL * D_MODEL)
#define W1_OFF   (WO_OFF + D_MODEL * D_MODEL)
#define W2_OFF   (W1_OFF + D_FF * D_MODEL)
#define WR_TOTAL (W2_OFF + D_MODEL * D_FF)
__device__ __half g_wh[(size_t)WR_TOTAL];

// ============================ helpers ============================
__device__ __forceinline__ void mma_f16(float* c,
    unsigned a0, unsigned a1, unsigned a2, unsigned a3,
    unsigned b0, unsigned b1)
{
    asm volatile(
        "mma.sync.aligned.m16n8k16.row.col.f32.f16.f16.f32 "
        "{%0,%1,%2,%3}, {%4,%5,%6,%7}, {%8,%9}, {%0,%1,%2,%3};"
        : "+f"(c[0]), "+f"(c[1]), "+f"(c[2]), "+f"(c[3])
        : "r"(a0), "r"(a1), "r"(a2), "r"(a3), "r"(b0), "r"(b1));
}

__device__ __forceinline__ void ldsm4(unsigned* r, unsigned addr) {
    asm volatile(
        "ldmatrix.sync.aligned.m8n8.x4.shared.b16 {%0,%1,%2,%3}, [%4];"
        : "=r"(r[0]), "=r"(r[1]), "=r"(r[2]), "=r"(r[3]) : "r"(addr));
}
__device__ __forceinline__ void ldsm4t(unsigned* r, unsigned addr) {
    asm volatile(
        "ldmatrix.sync.aligned.m8n8.x4.trans.shared.b16 {%0,%1,%2,%3}, [%4];"
        : "=r"(r[0]), "=r"(r[1]), "=r"(r[2]), "=r"(r[3]) : "r"(addr));
}

__device__ __forceinline__ void cp16(void* dst_sh, const void* src) {
    unsigned sa = (unsigned)__cvta_generic_to_shared(dst_sh);
    asm volatile("cp.async.cg.shared.global [%0], [%1], 16;" :: "r"(sa), "l"(src));
}
__device__ __forceinline__ void cp_commit() {
    asm volatile("cp.async.commit_group;");
}
template <int N>
__device__ __forceinline__ void cp_wait() {
    asm volatile("cp.async.wait_group %0;" :: "n"(N));
}

__device__ __forceinline__ float gelu_exact(float v) {
    return 0.5f * v * (1.0f + erff(v * 0.70710678118654752f));
}

__device__ __forceinline__ unsigned h2u(__half2 h) {
    unsigned u;
    *(__half2*)&u = h;
    return u;
}

// ============================ fp32 -> fp16 convert ============================
__global__ void __launch_bounds__(256) to_half_kernel(
    const float4* __restrict__ src, uint4* __restrict__ dst, int n8)
{
    int i = blockIdx.x * 256 + threadIdx.x;
    if (i < n8) {
        float4 v0 = src[2 * i], v1 = src[2 * i + 1];
        uint4 o;
        o.x = h2u(__floats2half2_rn(v0.x, v0.y));
        o.y = h2u(__floats2half2_rn(v0.z, v0.w));
        o.z = h2u(__floats2half2_rn(v1.x, v1.y));
        o.w = h2u(__floats2half2_rn(v1.z, v1.w));
        dst[i] = o;
    }
}

// ============================ LayerNorm (half output) ============================
__global__ void __launch_bounds__(256) ln_kernel(
    const float* __restrict__ x, const float* __restrict__ g,
    const float* __restrict__ b, __half* __restrict__ out)
{
    __shared__ float red[2][8];
    int row = blockIdx.x, tid = threadIdx.x;
    const float4* xr = (const float4*)(x + (size_t)row * D_MODEL);
    float4 v0 = xr[tid];
    float4 v1 = xr[tid + 256];
    float s  = v0.x + v0.y + v0.z + v0.w + v1.x + v1.y + v1.z + v1.w;
    float s2 = v0.x*v0.x + v0.y*v0.y + v0.z*v0.z + v0.w*v0.w
             + v1.x*v1.x + v1.y*v1.y + v1.z*v1.z + v1.w*v1.w;
    #pragma unroll
    for (int o = 16; o; o >>= 1) {
        s  += __shfl_xor_sync(0xffffffffu, s,  o);
        s2 += __shfl_xor_sync(0xffffffffu, s2, o);
    }
    if ((tid & 31) == 0) { red[0][tid >> 5] = s; red[1][tid >> 5] = s2; }
    __syncthreads();
    if (tid < 32) {
        float a = (tid < 8) ? red[0][tid] : 0.f;
        float c = (tid < 8) ? red[1][tid] : 0.f;
        #pragma unroll
        for (int o = 4; o; o >>= 1) {
            a += __shfl_xor_sync(0xffffffffu, a, o);
            c += __shfl_xor_sync(0xffffffffu, c, o);
        }
        if (tid == 0) { red[0][0] = a; red[1][0] = c; }
    }
    __syncthreads();
    float mean = red[0][0] * (1.f / D_MODEL);
    float var  = red[1][0] * (1.f / D_MODEL) - mean * mean;
    float rstd = rsqrtf(var + 1e-5f);

    const float4* gr = (const float4*)g;
    const float4* br = (const float4*)b;
    __half2* orow = (__half2*)(out + (size_t)row * D_MODEL);
    #pragma unroll
    for (int p = 0; p < 2; p++) {
        float4 v = p ? v1 : v0;
        float4 gw = gr[tid + p * 256];
        float4 bw = br[tid + p * 256];
        orow[2 * (tid + p * 256) + 0] = __floats2half2_rn(
            (v.x - mean) * rstd * gw.x + bw.x,
            (v.y - mean) * rstd * gw.y + bw.y);
        orow[2 * (tid + p * 256) + 1] = __floats2half2_rn(
            (v.z - mean) * rstd * gw.z + bw.z,
            (v.w - mean) * rstd * gw.w + bw.w);
    }
}

// ============================ fp16 mma GEMM: cp.async 3-stage + ldmatrix ============================
// EPI: 0 = bias -> half; 1 = bias + fp32 residual -> fp32; 2 = bias + GELU -> half
// Single barrier per ktile: wait<1> -> BAR -> prefetch(kb+2) -> compute(kb).
#define GBM 128
#define GBN 128
#define GBK 64
#define TILE_H (128 * 64)
#define NSTAGE 3
#define STAGE_H (2 * TILE_H)
#define GEMM_SMEM (NSTAGE * STAGE_H * 2)  // 98304 B

template <int EPI>
__global__ void __launch_bounds__(256, 2) gemm_kernel(
    const __half* __restrict__ A, const __half* __restrict__ B,
    const float* __restrict__ bias, const float* __restrict__ res,
    void* __restrict__ Cv, int M, int N, int K)
{
    extern __shared__ __half smh[];
    int tid = threadIdx.x;
    int bm = blockIdx.y, bn = blockIdx.x;
    int warp = tid >> 5, lane = tid & 31;
    int wm = warp >> 1, wn = warp & 1;
    int g = lane >> 2, c = lane & 3;

    int srow0 = tid >> 3, sc8 = tid & 7;
    const __half* Asrc0 = A + (size_t)(bm * GBM + srow0) * K + sc8 * 8;
    const __half* Bsrc0 = B + (size_t)(bn * GBN + srow0) * K + sc8 * 8;
    int sdst0 = srow0 * 64 + ((sc8 ^ (srow0 & 7)) << 3);

    float acc[2][8][4];
    #pragma unroll
    for (int mt = 0; mt < 2; mt++)
        #pragma unroll
        for (int nt = 0; nt < 8; nt++)
            #pragma unroll
            for (int q = 0; q < 4; q++) acc[mt][nt][q] = 0.f;

    int kt = K / GBK;

    unsigned smbase = (unsigned)__cvta_generic_to_shared(smh);
    int l7 = lane & 7;
    int arow = wm * 32 + l7 + ((lane >> 3) & 1) * 8;
    int brow = wn * 64 + l7 + (lane >> 4) * 8;
    unsigned abyte0 = smbase + arow * 128;
    unsigned bbyte0 = smbase + TILE_H * 2 + brow * 128;
    int kA = lane >> 4;
    int kB = (lane >> 3) & 1;

    #pragma unroll
    for (int s = 0; s < NSTAGE - 1; s++) {
        #pragma unroll
        for (int p = 0; p < 4; p++) {
            cp16(smh + s * STAGE_H + sdst0 + p * 2048,
                 Asrc0 + (size_t)(32 * p) * K + s * GBK);
            cp16(smh + s * STAGE_H + TILE_H + sdst0 + p * 2048,
                 Bsrc0 + (size_t)(32 * p) * K + s * GBK);
        }
        cp_commit();
    }

    for (int kb = 0; kb < kt; ++kb) {
        int cur = kb % NSTAGE;
        if (kb < kt - 1) cp_wait<1>(); else cp_wait<0>();
        __syncthreads();   // publish stage kb; all warps done reading (kb+2)%3

        if (kb + 2 < kt) {
            int nst = (kb + 2) % NSTAGE;
            #pragma unroll
            for (int p = 0; p < 4; p++) {
                cp16(smh + nst * STAGE_H + sdst0 + p * 2048,
                     Asrc0 + (size_t)(32 * p) * K + (kb + 2) * GBK);
                cp16(smh + nst * STAGE_H + TILE_H + sdst0 + p * 2048,
                     Bsrc0 + (size_t)(32 * p) * K + (kb + 2) * GBK);
            }
            cp_commit();
        }

        unsigned aB = abyte0 + cur * (STAGE_H * 2);
        unsigned bB = bbyte0 + cur * (STAGE_H * 2);

        #pragma unroll
        for (int kc = 0; kc < 4; kc++) {
            unsigned fa[2][4];
            #pragma unroll
            for (int mt = 0; mt < 2; mt++)
                ldsm4(fa[mt], aB + mt * (16 * 128) + ((unsigned)((2 * kc + kA) ^ l7) << 4));
            unsigned fb[4][4];
            #pragma unroll
            for (int p = 0; p < 4; p++)
                ldsm4(fb[p], bB + p * (16 * 128) + ((unsigned)((2 * kc + kB) ^ l7) << 4));
            #pragma unroll
            for (int mt = 0; mt < 2; mt++)
                #pragma unroll
                for (int nt = 0; nt < 8; nt++)
                    mma_f16(acc[mt][nt],
                            fa[mt][0], fa[mt][1], fa[mt][2], fa[mt][3],
                            fb[nt >> 1][(nt & 1) * 2], fb[nt >> 1][(nt & 1) * 2 + 1]);
        }
    }

    int row0g = bm * GBM + wm * 32;
    int col0g = bn * GBN + wn * 64;
    #pragma unroll
    for (int mt = 0; mt < 2; mt++)
        #pragma unroll
        for (int nt = 0; nt < 8; nt++)
            #pragma unroll
            for (int h2 = 0; h2 < 2; h2++) {
                int row = row0g + mt * 16 + h2 * 8 + g;
                int col = col0g + nt * 8 + 2 * c;
                float vx = acc[mt][nt][2 * h2 + 0] + bias[col];
                float vy = acc[mt][nt][2 * h2 + 1] + bias[col + 1];
                size_t off = (size_t)row * N + col;
                if (EPI == 0) {
                    __half* Ch = (__half*)Cv;
                    *(__half2*)(Ch + off) = __floats2half2_rn(vx, vy);
                } else if (EPI == 2) {
                    __half* Ch = (__half*)Cv;
                    *(__half2*)(Ch + off) =
                        __floats2half2_rn(gelu_exact(vx), gelu_exact(vy));
                } else {
                    float* Cf = (float*)Cv;
                    float2 r = *(const float2*)(res + off);
                    vx += r.x; vy += r.y;
                    *(float2*)(Cf + off) = make_float2(vx, vy);
                }
            }
}

// ============================ fp16 tensor-core flash attention ============================
// Double-buffered K/V, single barrier per tile, heavy-first scheduling.
#define QS_OFF 0                       // 2 t x 128x64 halfs (32 KB)
#define KS_OFF (2 * 128 * 64)          // 2 buf x 2 t x 64x64 (32 KB)
#define VS_OFF (KS_OFF + 2 * 2 * 64 * 64)
#define PS_OFF (VS_OFF + 2 * 2 * 64 * 64)  // 8 warps x 16x64 (16 KB)
#define ATT_HALFS (PS_OFF + 8 * 16 * 64)
#define ATT_SMEM (ATT_HALFS * 2)       // 114688 B
#define NEG_BIG (-1e30f)

__global__ void __launch_bounds__(256, 1) attn_kernel(
    const __half* __restrict__ qkv, const float* __restrict__ slopes,
    __half* __restrict__ out)
{
    extern __shared__ __half smA[];
    int qi = (int)gridDim.x - 1 - (int)blockIdx.x;   // heavy blocks first
    int h = blockIdx.y, b = blockIdx.z;
    int tid = threadIdx.x, warp = tid >> 5, lane = tid & 31;
    int g = lane >> 2, c = lane & 3, l7 = lane & 7;
    int q0 = qi * 128;
    float slope = slopes[h];
    const float scale = 0.08838834764831845f;   // 1/sqrt(128)

    const __half* qb = qkv + (size_t)(b * SEQ) * QKV_N + h * HD;
    const __half* kb = qb + D_MODEL;
    const __half* vb = qb + 2 * D_MODEL;

    unsigned smbase = (unsigned)__cvta_generic_to_shared(smA);
    __half* Pw = smA + PS_OFF + warp * 1024;
    unsigned pbase = smbase + (PS_OFF + warp * 1024) * 2;

    // stage Q (resident)
    for (int i = tid; i < 2048; i += 256) {
        int row = i >> 4, cc = i & 15;
        int t = cc >> 3, cw = cc & 7;
        cp16(smA + QS_OFF + t * 8192 + row * 64 + ((cw ^ (row & 7)) << 3),
             qb + (size_t)(q0 + row) * QKV_N + cc * 8);
    }
    cp_commit();

    // stage K/V tile 0 into buffer 0
    for (int i = tid; i < 1024; i += 256) {
        int row = i >> 4, cc = i & 15;
        int t = cc >> 3, cw = cc & 7;
        int d = row * 64 + ((cw ^ (row & 7)) << 3);
        cp16(smA + KS_OFF + t * 4096 + d, kb + (size_t)row * QKV_N + cc * 8);
        cp16(smA + VS_OFF + t * 4096 + d, vb + (size_t)row * QKV_N + cc * 8);
    }
    cp_commit();

    float m0 = NEG_BIG, m1 = NEG_BIG, l0 = 0.f, l1 = 0.f;
    float oc[16][4];
    #pragma unroll
    for (int nt = 0; nt < 16; nt++)
        #pragma unroll
        for (int q = 0; q < 4; q++) oc[nt][q] = 0.f;

    int rowA = 16 * warp + g;
    int qr0 = q0 + rowA, qr1 = qr0 + 8;

    int a_roff = ((lane >> 3) & 1) * 8 + l7;
    int a_csel = lane >> 4;
    int b_roff = (lane >> 4) * 8 + l7;
    int b_csel = (lane >> 3) & 1;
    int v_roff = ((lane >> 3) & 1) * 8 + l7;
    int v_csel = lane >> 4;

    int ntiles = 2 * qi + 2;
    for (int jt = 0; jt < ntiles; jt++) {
        int bsel = jt & 1;
        cp_wait<0>();
        __syncthreads();

        if (jt + 1 < ntiles) {
            int j1 = (jt + 1) * 64;
            int ns = bsel ^ 1;
            for (int i = tid; i < 1024; i += 256) {
                int row = i >> 4, cc = i & 15;
                int t = cc >> 3, cw = cc & 7;
                int d = row * 64 + ((cw ^ (row & 7)) << 3);
                cp16(smA + KS_OFF + ns * 8192 + t * 4096 + d,
                     kb + (size_t)(j1 + row) * QKV_N + cc * 8);
                cp16(smA + VS_OFF + ns * 8192 + t * 4096 + d,
                     vb + (size_t)(j1 + row) * QKV_N + cc * 8);
            }
            cp_commit();
        }

        int j0 = jt * 64;
        unsigned kbb = smbase + (KS_OFF + bsel * 8192) * 2;
        unsigned vbb = smbase + (VS_OFF + bsel * 8192) * 2;

        float sc[8][4];
        #pragma unroll
        for (int nt = 0; nt < 8; nt++)
            #pragma unroll
            for (int q = 0; q < 4; q++) sc[nt][q] = 0.f;

        #pragma unroll
        for (int kc = 0; kc < 8; kc++) {
            int t = kc >> 2, k2 = kc & 3;
            unsigned fa[4];
            {
                int row = warp * 16 + a_roff;
                unsigned addr = smbase +
                    (QS_OFF + t * 8192 + row * 64 + (((k2 * 2 + a_csel) ^ l7) << 3)) * 2;
                ldsm4(fa, addr);
            }
            unsigned fb[4][4];
            #pragma unroll
            for (int p = 0; p < 4; p++) {
                int key = 16 * p + b_roff;
                unsigned addr = kbb +
                    (t * 4096 + key * 64 + (((k2 * 2 + b_csel) ^ l7) << 3)) * 2;
                ldsm4(fb[p], addr);
            }
            #pragma unroll
            for (int nt = 0; nt < 8; nt++)
                mma_f16(sc[nt], fa[0], fa[1], fa[2], fa[3],
                        fb[nt >> 1][(nt & 1) * 2], fb[nt >> 1][(nt & 1) * 2 + 1]);
        }

        bool masked = (jt >= 2 * qi);
        float tm0 = NEG_BIG, tm1 = NEG_BIG;
        #pragma unroll
        for (int nt = 0; nt < 8; nt++) {
            #pragma unroll
            for (int j = 0; j < 2; j++) {
                int col = j0 + nt * 8 + 2 * c + j;
                float s0 = sc[nt][j]     * scale + slope * (float)(col - qr0);
                float s1 = sc[nt][2 + j] * scale + slope * (float)(col - qr1);
                if (masked) {
                    if (col > qr0) s0 = NEG_BIG;
                    if (col > qr1) s1 = NEG_BIG;
                }
                sc[nt][j] = s0; sc[nt][2 + j] = s1;
                tm0 = fmaxf(tm0, s0); tm1 = fmaxf(tm1, s1);
            }
        }
        #pragma unroll
        for (int o = 1; o < 4; o <<= 1) {
            tm0 = fmaxf(tm0, __shfl_xor_sync(0xffffffffu, tm0, o));
            tm1 = fmaxf(tm1, __shfl_xor_sync(0xffffffffu, tm1, o));
        }
        float mn0 = fmaxf(m0, tm0), mn1 = fmaxf(m1, tm1);
        float alpha0 = __expf(m0 - mn0), alpha1 = __expf(m1 - mn1);
        float rs0 = 0.f, rs1 = 0.f;
        #pragma unroll
        for (int nt = 0; nt < 8; nt++) {
            #pragma unroll
            for (int j = 0; j < 2; j++) {
                float p0 = __expf(sc[nt][j]     - mn0);
                float p1 = __expf(sc[nt][2 + j] - mn1);
                sc[nt][j] = p0; sc[nt][2 + j] = p1;
                rs0 += p0; rs1 += p1;
            }
        }
        #pragma unroll
        for (int o = 1; o < 4; o <<= 1) {
            rs0 += __shfl_xor_sync(0xffffffffu, rs0, o);
            rs1 += __shfl_xor_sync(0xffffffffu, rs1, o);
        }
        l0 = l0 * alpha0 + rs0;
        l1 = l1 * alpha1 + rs1;
        m0 = mn0; m1 = mn1;
        #pragma unroll
        for (int nt = 0; nt < 16; nt++) {
            oc[nt][0] *= alpha0; oc[nt][1] *= alpha0;
            oc[nt][2] *= alpha1; oc[nt][3] *= alpha1;
        }

        __syncwarp();
        #pragma unroll
        for (int nt = 0; nt < 8; nt++) {
            *(__half2*)(Pw + g * 64 + ((nt ^ (g & 7)) << 3) + 2 * c) =
                __floats2half2_rn(sc[nt][0], sc[nt][1]);
            *(__half2*)(Pw + (g + 8) * 64 + ((nt ^ (g & 7)) << 3) + 2 * c) =
                __floats2half2_rn(sc[nt][2], sc[nt][3]);
        }
        __syncwarp();

        #pragma unroll
        for (int kc2 = 0; kc2 < 4; kc2++) {
            unsigned fa[4];
            {
                unsigned addr = pbase +
                    (a_roff * 64 + (((kc2 * 2 + a_csel) ^ l7) << 3)) * 2;
                ldsm4(fa, addr);
            }
            unsigned fv[8][4];
            #pragma unroll
            for (int nv = 0; nv < 8; nv++) {
                int t = nv >> 2;
                int cw = (nv & 3) * 2 + v_csel;
                int key = kc2 * 16 + v_roff;
                unsigned addr = vbb +
                    (t * 4096 + key * 64 + ((cw ^ l7) << 3)) * 2;
                ldsm4t(fv[nv], addr);
            }
            #pragma unroll
            for (int nt = 0; nt < 16; nt++)
                mma_f16(oc[nt], fa[0], fa[1], fa[2], fa[3],
                        fv[nt >> 1][(nt & 1) * 2], fv[nt >> 1][(nt & 1) * 2 + 1]);
        }
    }

    float inv0 = 1.f / l0, inv1 = 1.f / l1;
    __half* ob  = out + (size_t)(b * SEQ + qr0) * D_MODEL + h * HD;
    __half* ob1 = ob + 8 * D_MODEL;
    #pragma unroll
    for (int nt = 0; nt < 16; nt++) {
        *(__half2*)&ob[nt * 8 + 2 * c] =
            __floats2half2_rn(oc[nt][0] * inv0, oc[nt][1] * inv0);
        *(__half2*)&ob1[nt * 8 + 2 * c] =
            __floats2half2_rn(oc[nt][2] * inv1, oc[nt][3] * inv1);
    }
}

// ============================ launch ============================
extern "C" void kernel_launch(void* const* d_in, const int* in_sizes, int n_in,
                              void* d_out, int out_size)
{
    const float* x      = (const float*)d_in[0];
    const float* ln1_w  = (const float*)d_in[1];
    const float* ln1_b  = (const float*)d_in[2];
    const float* Wqkv   = (const float*)d_in[3];
    const float* bqkv   = (const float*)d_in[4];
    const float* Wo     = (const float*)d_in[5];
    const float* bo     = (const float*)d_in[6];
    const float* ln2_w  = (const float*)d_in[7];
    const float* ln2_b  = (const float*)d_in[8];
    const float* W1     = (const float*)d_in[9];
    const float* b1     = (const float*)d_in[10];
    const float* W2     = (const float*)d_in[11];
    const float* b2     = (const float*)d_in[12];
    const float* slopes = (const float*)d_in[13];
    float* out = (float*)d_out;

    __half *h, *qkv, *attn, *mlp, *wh;
    cudaGetSymbolAddress((void**)&h,    g_h);
    cudaGetSymbolAddress((void**)&qkv,  g_qkv);
    cudaGetSymbolAddress((void**)&attn, g_attn);
    cudaGetSymbolAddress((void**)&mlp,  g_mlp);
    cudaGetSymbolAddress((void**)&wh,   g_wh);

    cudaFuncSetAttribute(attn_kernel,
                         cudaFuncAttributeMaxDynamicSharedMemorySize, ATT_SMEM);
    cudaFuncSetAttribute(gemm_kernel<0>,
                         cudaFuncAttributeMaxDynamicSharedMemorySize, GEMM_SMEM);
    cudaFuncSetAttribute(gemm_kernel<1>,
                         cudaFuncAttributeMaxDynamicSharedMemorySize, GEMM_SMEM);
    cudaFuncSetAttribute(gemm_kernel<2>,
                         cudaFuncAttributeMaxDynamicSharedMemorySize, GEMM_SMEM);

    // 0. convert weights to half (four separate launches — round-11 exact)
    {
        int n8;
        n8 = 3 * D_MODEL * D_MODEL / 8;
        to_half_kernel<<<(n8 + 255) / 256, 256>>>((const float4*)Wqkv,
            (uint4*)(wh + WQKV_OFF), n8);
        n8 = D_MODEL * D_MODEL / 8;
        to_half_kernel<<<(n8 + 255) / 256, 256>>>((const float4*)Wo,
            (uint4*)(wh + WO_OFF), n8);
        n8 = D_FF * D_MODEL / 8;
        to_half_kernel<<<(n8 + 255) / 256, 256>>>((const float4*)W1,
            (uint4*)(wh + W1_OFF), n8);
        n8 = D_MODEL * D_FF / 8;
        to_half_kernel<<<(n8 + 255) / 256, 256>>>((const float4*)W2,
            (uint4*)(wh + W2_OFF), n8);
    }

    // 1. LN1 -> half
    ln_kernel<<<ROWS, 256>>>(x, ln1_w, ln1_b, h);
    // 2. QKV GEMM -> half
    gemm_kernel<0><<<dim3(QKV_N / GBN, ROWS / GBM), 256, GEMM_SMEM>>>(
        h, wh + WQKV_OFF, bqkv, nullptr, qkv, ROWS, QKV_N, D_MODEL);
    // 3. Flash attention with ALiBi (fp16 mma) -> half
    attn_kernel<<<dim3(SEQ / 128, NH, BATCH), 256, ATT_SMEM>>>(qkv, slopes, attn);
    // 4. O projection + residual (x) -> d_out fp32
    gemm_kernel<1><<<dim3(D_MODEL / GBN, ROWS / GBM), 256, GEMM_SMEM>>>(
        attn, wh + WO_OFF, bo, x, out, ROWS, D_MODEL, D_MODEL);
    // 5. LN2 -> half
    ln_kernel<<<ROWS, 256>>>(out, ln2_w, ln2_b, h);
    // 6. MLP up + GELU -> half
    gemm_kernel<2><<<dim3(D_FF / GBN, ROWS / GBM), 256, GEMM_SMEM>>>(
        h, wh + W1_OFF, b1, nullptr, mlp, ROWS, D_FF, D_MODEL);
    // 7. MLP down + residual (x1 in d_out) -> d_out fp32 final
    gemm_kernel<1><<<dim3(D_MODEL / GBN, ROWS / GBM), 256, GEMM_SMEM>>>(
        mlp, wh + W2_OFF, b2, out, out, ROWS, D_MODEL, D_FF);
}

// round 17
// speedup vs baseline: 1.5797x; 1.0201x over previous
#include <cuda_runtime.h>
#include <cuda_fp16.h>
#include <math.h>

#define D_MODEL 2048
#define NH 16
#define HD 128
#define SEQ 2048
#define BATCH 4
#define ROWS (BATCH * SEQ)       // 8192
#define D_FF 8192
#define QKV_N (3 * D_MODEL)      // 6144

// -------- scratch (static device globals; no cudaMalloc allowed) --------
__device__ __half g_h[(size_t)ROWS * D_MODEL];     // LN output (half)
__device__ __half g_qkv[(size_t)ROWS * QKV_N];     // fused QKV (half)
__device__ __half g_attn[(size_t)ROWS * D_MODEL];  // attention out (half)
__device__ __half g_mlp[(size_t)ROWS * D_FF];      // MLP hidden (half)
// half weights: Wqkv | Wo | W1 | W2
#define WQKV_OFF 0
#define WO_OFF   (3 * D_MODEL * D_MODEL)
#define W1_OFF   (WO_OFF + D_MODEL * D_MODEL)
#define W2_OFF   (W1_OFF + D_FF * D_MODEL)
#define WR_TOTAL (W2_OFF + D_MODEL * D_FF)
__device__ __half g_wh[(size_t)WR_TOTAL];

// ============================ helpers ============================
__device__ __forceinline__ void mma_f16(float* c,
    unsigned a0, unsigned a1, unsigned a2, unsigned a3,
    unsigned b0, unsigned b1)
{
    asm volatile(
        "mma.sync.aligned.m16n8k16.row.col.f32.f16.f16.f32 "
        "{%0,%1,%2,%3}, {%4,%5,%6,%7}, {%8,%9}, {%0,%1,%2,%3};"
        : "+f"(c[0]), "+f"(c[1]), "+f"(c[2]), "+f"(c[3])
        : "r"(a0), "r"(a1), "r"(a2), "r"(a3), "r"(b0), "r"(b1));
}

__device__ __forceinline__ void ldsm4(unsigned* r, unsigned addr) {
    asm volatile(
        "ldmatrix.sync.aligned.m8n8.x4.shared.b16 {%0,%1,%2,%3}, [%4];"
        : "=r"(r[0]), "=r"(r[1]), "=r"(r[2]), "=r"(r[3]) : "r"(addr));
}
__device__ __forceinline__ void ldsm4t(unsigned* r, unsigned addr) {
    asm volatile(
        "ldmatrix.sync.aligned.m8n8.x4.trans.shared.b16 {%0,%1,%2,%3}, [%4];"
        : "=r"(r[0]), "=r"(r[1]), "=r"(r[2]), "=r"(r[3]) : "r"(addr));
}

__device__ __forceinline__ void cp16(void* dst_sh, const void* src) {
    unsigned sa = (unsigned)__cvta_generic_to_shared(dst_sh);
    asm volatile("cp.async.cg.shared.global [%0], [%1], 16;" :: "r"(sa), "l"(src));
}
__device__ __forceinline__ void cp_commit() {
    asm volatile("cp.async.commit_group;");
}
template <int N>
__device__ __forceinline__ void cp_wait() {
    asm volatile("cp.async.wait_group %0;" :: "n"(N));
}

__device__ __forceinline__ float gelu_exact(float v) {
    return 0.5f * v * (1.0f + erff(v * 0.70710678118654752f));
}

__device__ __forceinline__ unsigned h2u(__half2 h) {
    unsigned u;
    *(__half2*)&u = h;
    return u;
}

// ============================ fp32 -> fp16 convert ============================
__global__ void __launch_bounds__(256) to_half_kernel(
    const float4* __restrict__ src, uint4* __restrict__ dst, int n8)
{
    int i = blockIdx.x * 256 + threadIdx.x;
    if (i < n8) {
        float4 v0 = src[2 * i], v1 = src[2 * i + 1];
        uint4 o;
        o.x = h2u(__floats2half2_rn(v0.x, v0.y));
        o.y = h2u(__floats2half2_rn(v0.z, v0.w));
        o.z = h2u(__floats2half2_rn(v1.x, v1.y));
        o.w = h2u(__floats2half2_rn(v1.z, v1.w));
        dst[i] = o;
    }
}

// ============================ LayerNorm (half output) ============================
__global__ void __launch_bounds__(256) ln_kernel(
    const float* __restrict__ x, const float* __restrict__ g,
    const float* __restrict__ b, __half* __restrict__ out)
{
    __shared__ float red[2][8];
    int row = blockIdx.x, tid = threadIdx.x;
    const float4* xr = (const float4*)(x + (size_t)row * D_MODEL);
    float4 v0 = xr[tid];
    float4 v1 = xr[tid + 256];
    float s  = v0.x + v0.y + v0.z + v0.w + v1.x + v1.y + v1.z + v1.w;
    float s2 = v0.x*v0.x + v0.y*v0.y + v0.z*v0.z + v0.w*v0.w
             + v1.x*v1.x + v1.y*v1.y + v1.z*v1.z + v1.w*v1.w;
    #pragma unroll
    for (int o = 16; o; o >>= 1) {
        s  += __shfl_xor_sync(0xffffffffu, s,  o);
        s2 += __shfl_xor_sync(0xffffffffu, s2, o);
    }
    if ((tid & 31) == 0) { red[0][tid >> 5] = s; red[1][tid >> 5] = s2; }
    __syncthreads();
    if (tid < 32) {
        float a = (tid < 8) ? red[0][tid] : 0.f;
        float c = (tid < 8) ? red[1][tid] : 0.f;
        #pragma unroll
        for (int o = 4; o; o >>= 1) {
            a += __shfl_xor_sync(0xffffffffu, a, o);
            c += __shfl_xor_sync(0xffffffffu, c, o);
        }
        if (tid == 0) { red[0][0] = a; red[1][0] = c; }
    }
    __syncthreads();
    float mean = red[0][0] * (1.f / D_MODEL);
    float var  = red[1][0] * (1.f / D_MODEL) - mean * mean;
    float rstd = rsqrtf(var + 1e-5f);

    const float4* gr = (const float4*)g;
    const float4* br = (const float4*)b;
    __half2* orow = (__half2*)(out + (size_t)row * D_MODEL);
    #pragma unroll
    for (int p = 0; p < 2; p++) {
        float4 v = p ? v1 : v0;
        float4 gw = gr[tid + p * 256];
        float4 bw = br[tid + p * 256];
        orow[2 * (tid + p * 256) + 0] = __floats2half2_rn(
            (v.x - mean) * rstd * gw.x + bw.x,
            (v.y - mean) * rstd * gw.y + bw.y);
        orow[2 * (tid + p * 256) + 1] = __floats2half2_rn(
            (v.z - mean) * rstd * gw.z + bw.z,
            (v.w - mean) * rstd * gw.w + bw.w);
    }
}

// ============================ fp16 mma GEMM: cp.async 3-stage + ldmatrix ============================
// (round-11/14 proven config, byte-identical)
#define GBM 128
#define GBN 128
#define GBK 64
#define TILE_H (128 * 64)
#define NSTAGE 3
#define STAGE_H (2 * TILE_H)
#define GEMM_SMEM (NSTAGE * STAGE_H * 2)  // 98304 B

template <int EPI>
__global__ void __launch_bounds__(256, 2) gemm_kernel(
    const __half* __restrict__ A, const __half* __restrict__ B,
    const float* __restrict__ bias, const float* __restrict__ res,
    void* __restrict__ Cv, int M, int N, int K)
{
    extern __shared__ __half smh[];
    int tid = threadIdx.x;
    int bm = blockIdx.y, bn = blockIdx.x;
    int warp = tid >> 5, lane = tid & 31;
    int wm = warp >> 1, wn = warp & 1;
    int g = lane >> 2, c = lane & 3;

    int srow0 = tid >> 3, sc8 = tid & 7;
    const __half* Asrc0 = A + (size_t)(bm * GBM + srow0) * K + sc8 * 8;
    const __half* Bsrc0 = B + (size_t)(bn * GBN + srow0) * K + sc8 * 8;
    int sdst0 = srow0 * 64 + ((sc8 ^ (srow0 & 7)) << 3);

    float acc[2][8][4];
    #pragma unroll
    for (int mt = 0; mt < 2; mt++)
        #pragma unroll
        for (int nt = 0; nt < 8; nt++)
            #pragma unroll
            for (int q = 0; q < 4; q++) acc[mt][nt][q] = 0.f;

    int kt = K / GBK;

    unsigned smbase = (unsigned)__cvta_generic_to_shared(smh);
    int l7 = lane & 7;
    int arow = wm * 32 + l7 + ((lane >> 3) & 1) * 8;
    int brow = wn * 64 + l7 + (lane >> 4) * 8;
    unsigned abyte0 = smbase + arow * 128;
    unsigned bbyte0 = smbase + TILE_H * 2 + brow * 128;
    int kA = lane >> 4;
    int kB = (lane >> 3) & 1;

    #pragma unroll
    for (int s = 0; s < NSTAGE - 1; s++) {
        #pragma unroll
        for (int p = 0; p < 4; p++) {
            cp16(smh + s * STAGE_H + sdst0 + p * 2048,
                 Asrc0 + (size_t)(32 * p) * K + s * GBK);
            cp16(smh + s * STAGE_H + TILE_H + sdst0 + p * 2048,
                 Bsrc0 + (size_t)(32 * p) * K + s * GBK);
        }
        cp_commit();
    }

    for (int kb = 0; kb < kt; ++kb) {
        int cur = kb % NSTAGE;
        if (kb < kt - 1) cp_wait<1>(); else cp_wait<0>();
        __syncthreads();

        if (kb + 2 < kt) {
            int nst = (kb + 2) % NSTAGE;
            #pragma unroll
            for (int p = 0; p < 4; p++) {
                cp16(smh + nst * STAGE_H + sdst0 + p * 2048,
                     Asrc0 + (size_t)(32 * p) * K + (kb + 2) * GBK);
                cp16(smh + nst * STAGE_H + TILE_H + sdst0 + p * 2048,
                     Bsrc0 + (size_t)(32 * p) * K + (kb + 2) * GBK);
            }
            cp_commit();
        }

        unsigned aB = abyte0 + cur * (STAGE_H * 2);
        unsigned bB = bbyte0 + cur * (STAGE_H * 2);

        #pragma unroll
        for (int kc = 0; kc < 4; kc++) {
            unsigned fa[2][4];
            #pragma unroll
            for (int mt = 0; mt < 2; mt++)
                ldsm4(fa[mt], aB + mt * (16 * 128) + ((unsigned)((2 * kc + kA) ^ l7) << 4));
            unsigned fb[4][4];
            #pragma unroll
            for (int p = 0; p < 4; p++)
                ldsm4(fb[p], bB + p * (16 * 128) + ((unsigned)((2 * kc + kB) ^ l7) << 4));
            #pragma unroll
            for (int mt = 0; mt < 2; mt++)
                #pragma unroll
                for (int nt = 0; nt < 8; nt++)
                    mma_f16(acc[mt][nt],
                            fa[mt][0], fa[mt][1], fa[mt][2], fa[mt][3],
                            fb[nt >> 1][(nt & 1) * 2], fb[nt >> 1][(nt & 1) * 2 + 1]);
        }
    }

    int row0g = bm * GBM + wm * 32;
    int col0g = bn * GBN + wn * 64;
    #pragma unroll
    for (int mt = 0; mt < 2; mt++)
        #pragma unroll
        for (int nt = 0; nt < 8; nt++)
            #pragma unroll
            for (int h2 = 0; h2 < 2; h2++) {
                int row = row0g + mt * 16 + h2 * 8 + g;
                int col = col0g + nt * 8 + 2 * c;
                float vx = acc[mt][nt][2 * h2 + 0] + bias[col];
                float vy = acc[mt][nt][2 * h2 + 1] + bias[col + 1];
                size_t off = (size_t)row * N + col;
                if (EPI == 0) {
                    __half* Ch = (__half*)Cv;
                    *(__half2*)(Ch + off) = __floats2half2_rn(vx, vy);
                } else if (EPI == 2) {
                    __half* Ch = (__half*)Cv;
                    *(__half2*)(Ch + off) =
                        __floats2half2_rn(gelu_exact(vx), gelu_exact(vy));
                } else {
                    float* Cf = (float*)Cv;
                    float2 r = *(const float2*)(res + off);
                    vx += r.x; vy += r.y;
                    *(float2*)(Cf + off) = make_float2(vx, vy);
                }
            }
}

// ============================ fp16 tensor-core flash attention (KV tile 128) ============================
// CTA: 128 q x 128-key tiles, 8 warps (16 q-rows each). Double-buffered K/V.
// Half the tiles of the KV-64 version: half the barriers/waits/rescales.
// smem layout (halfs): Q[2 slab][128r][64], K/V[2 buf][2 slab][128r][64],
// P[8 warp][2 slab][16r][64]. All rows 64-half (128B) with chunk XOR swizzle.
#define AQS_OFF 0                          // 16384 halfs (32 KB)
#define AKS_OFF 16384                      // 2 buf x 16384 (64 KB)
#define AVS_OFF (AKS_OFF + 2 * 16384)      // 2 buf x 16384 (64 KB)
#define APS_OFF (AVS_OFF + 2 * 16384)      // 8 x 2048 (32 KB)
#define ATT_HALFS (APS_OFF + 8 * 2048)     // 98304 halfs
#define ATT_SMEM (ATT_HALFS * 2)           // 196608 B
#define NEG_BIG (-1e30f)

__global__ void __launch_bounds__(256, 1) attn_kernel(
    const __half* __restrict__ qkv, const float* __restrict__ slopes,
    __half* __restrict__ out)
{
    extern __shared__ __half smA[];
    int qi = (int)gridDim.x - 1 - (int)blockIdx.x;   // heavy blocks first
    int h = blockIdx.y, b = blockIdx.z;
    int tid = threadIdx.x, warp = tid >> 5, lane = tid & 31;
    int g = lane >> 2, c = lane & 3, l7 = lane & 7;
    int q0 = qi * 128;
    float slope = slopes[h];
    const float scale = 0.08838834764831845f;   // 1/sqrt(128)

    const __half* qb = qkv + (size_t)(b * SEQ) * QKV_N + h * HD;
    const __half* kb = qb + D_MODEL;
    const __half* vb = qb + 2 * D_MODEL;

    unsigned smbase = (unsigned)__cvta_generic_to_shared(smA);
    __half* Pw = smA + APS_OFF + warp * 2048;
    unsigned pbase = smbase + (APS_OFF + warp * 2048) * 2;

    // stage Q (resident): 128 rows x 16 chunks (group 0)
    for (int i = tid; i < 2048; i += 256) {
        int row = i >> 4, cc = i & 15;
        int t = cc >> 3, cw = cc & 7;
        cp16(smA + AQS_OFF + t * 8192 + row * 64 + ((cw ^ (row & 7)) << 3),
             qb + (size_t)(q0 + row) * QKV_N + cc * 8);
    }
    cp_commit();

    // stage K/V tile 0 into buffer 0 (group 1): 128 rows x 16 chunks each
    for (int i = tid; i < 2048; i += 256) {
        int row = i >> 4, cc = i & 15;
        int t = cc >> 3, cw = cc & 7;
        int d = t * 8192 + row * 64 + ((cw ^ (row & 7)) << 3);
        cp16(smA + AKS_OFF + d, kb + (size_t)row * QKV_N + cc * 8);
        cp16(smA + AVS_OFF + d, vb + (size_t)row * QKV_N + cc * 8);
    }
    cp_commit();

    float m0 = NEG_BIG, m1 = NEG_BIG, l0 = 0.f, l1 = 0.f;
    float oc[16][4];
    #pragma unroll
    for (int nt = 0; nt < 16; nt++)
        #pragma unroll
        for (int q = 0; q < 4; q++) oc[nt][q] = 0.f;

    int rowA = 16 * warp + g;
    int qr0 = q0 + rowA, qr1 = qr0 + 8;

    int a_roff = ((lane >> 3) & 1) * 8 + l7;
    int a_csel = lane >> 4;
    int b_roff = (lane >> 4) * 8 + l7;
    int b_csel = (lane >> 3) & 1;
    int v_roff = ((lane >> 3) & 1) * 8 + l7;
    int v_csel = lane >> 4;

    int ntiles = qi + 1;
    for (int jt = 0; jt < ntiles; jt++) {
        int bsel = jt & 1;
        cp_wait<0>();      // tile jt (and Q on first iter) complete
        __syncthreads();   // all warps done reading buffer (jt+1)&1

        // prefetch K/V tile jt+1 into the other buffer
        if (jt + 1 < ntiles) {
            int j1 = (jt + 1) * 128;
            int ns = bsel ^ 1;
            for (int i = tid; i < 2048; i += 256) {
                int row = i >> 4, cc = i & 15;
                int t = cc >> 3, cw = cc & 7;
                int d = t * 8192 + row * 64 + ((cw ^ (row & 7)) << 3);
                cp16(smA + AKS_OFF + ns * 16384 + d,
                     kb + (size_t)(j1 + row) * QKV_N + cc * 8);
                cp16(smA + AVS_OFF + ns * 16384 + d,
                     vb + (size_t)(j1 + row) * QKV_N + cc * 8);
            }
            cp_commit();
        }

        int j0 = jt * 128;
        unsigned kbb = smbase + (AKS_OFF + bsel * 16384) * 2;
        unsigned vbb = smbase + (AVS_OFF + bsel * 16384) * 2;

        // ---- S = Q K^T ----
        float sc[16][4];
        #pragma unroll
        for (int nt = 0; nt < 16; nt++)
            #pragma unroll
            for (int q = 0; q < 4; q++) sc[nt][q] = 0.f;

        #pragma unroll
        for (int kc = 0; kc < 8; kc++) {
            int t = kc >> 2, k2 = kc & 3;
            unsigned fa[4];
            {
                int row = warp * 16 + a_roff;
                unsigned addr = smbase +
                    (AQS_OFF + t * 8192 + row * 64 + (((k2 * 2 + a_csel) ^ l7) << 3)) * 2;
                ldsm4(fa, addr);
            }
            unsigned fb[8][4];
            #pragma unroll
            for (int p = 0; p < 8; p++) {
                int key = 16 * p + b_roff;
                unsigned addr = kbb +
                    (t * 8192 + key * 64 + (((k2 * 2 + b_csel) ^ l7) << 3)) * 2;
                ldsm4(fb[p], addr);
            }
            #pragma unroll
            for (int nt = 0; nt < 16; nt++)
                mma_f16(sc[nt], fa[0], fa[1], fa[2], fa[3],
                        fb[nt >> 1][(nt & 1) * 2], fb[nt >> 1][(nt & 1) * 2 + 1]);
        }

        // ---- scale + ALiBi (row-constant dropped; softmax-invariant) + causal ----
        bool masked = (jt == qi);
        float cbase = (float)(j0 + 2 * c);
        float tm0 = NEG_BIG, tm1 = NEG_BIG;
        #pragma unroll
        for (int nt = 0; nt < 16; nt++) {
            float colf = cbase + (float)(nt * 8);
            #pragma unroll
            for (int j = 0; j < 2; j++) {
                float s0 = fmaf(slope, colf + j, sc[nt][j] * scale);
                float s1 = fmaf(slope, colf + j, sc[nt][2 + j] * scale);
                if (masked) {
                    int col = j0 + nt * 8 + 2 * c + j;
                    if (col > qr0) s0 = NEG_BIG;
                    if (col > qr1) s1 = NEG_BIG;
                }
                sc[nt][j] = s0; sc[nt][2 + j] = s1;
                tm0 = fmaxf(tm0, s0); tm1 = fmaxf(tm1, s1);
            }
        }
        #pragma unroll
        for (int o = 1; o < 4; o <<= 1) {
            tm0 = fmaxf(tm0, __shfl_xor_sync(0xffffffffu, tm0, o));
            tm1 = fmaxf(tm1, __shfl_xor_sync(0xffffffffu, tm1, o));
        }
        float mn0 = fmaxf(m0, tm0), mn1 = fmaxf(m1, tm1);
        float alpha0 = __expf(m0 - mn0), alpha1 = __expf(m1 - mn1);
        float rs0 = 0.f, rs1 = 0.f;
        #pragma unroll
        for (int nt = 0; nt < 16; nt++) {
            #pragma unroll
            for (int j = 0; j < 2; j++) {
                float p0 = __expf(sc[nt][j]     - mn0);
                float p1 = __expf(sc[nt][2 + j] - mn1);
                sc[nt][j] = p0; sc[nt][2 + j] = p1;
                rs0 += p0; rs1 += p1;
            }
        }
        #pragma unroll
        for (int o = 1; o < 4; o <<= 1) {
            rs0 += __shfl_xor_sync(0xffffffffu, rs0, o);
            rs1 += __shfl_xor_sync(0xffffffffu, rs1, o);
        }
        l0 = l0 * alpha0 + rs0;
        l1 = l1 * alpha1 + rs1;
        m0 = mn0; m1 = mn1;
        #pragma unroll
        for (int nt = 0; nt < 16; nt++) {
            oc[nt][0] *= alpha0; oc[nt][1] *= alpha0;
            oc[nt][2] *= alpha1; oc[nt][3] *= alpha1;
        }

        // ---- stage P (half, swizzled 16x128 per warp: 2 slabs of 64) ----
        __syncwarp();
        #pragma unroll
        for (int nt = 0; nt < 16; nt++) {
            int t = nt >> 3, cw = nt & 7;
            __half* base = Pw + t * 1024;
            *(__half2*)(base + g * 64 + ((cw ^ (g & 7)) << 3) + 2 * c) =
                __floats2half2_rn(sc[nt][0], sc[nt][1]);
            *(__half2*)(base + (g + 8) * 64 + ((cw ^ (g & 7)) << 3) + 2 * c) =
                __floats2half2_rn(sc[nt][2], sc[nt][3]);
        }
        __syncwarp();

        // ---- O += P @ V  (k = 128 keys in 8 steps of 16) ----
        #pragma unroll
        for (int kc2 = 0; kc2 < 8; kc2++) {
            int t = kc2 >> 2, k2 = kc2 & 3;
            unsigned fa[4];
            {
                unsigned addr = pbase +
                    (t * 1024 + a_roff * 64 + (((k2 * 2 + a_csel) ^ l7) << 3)) * 2;
                ldsm4(fa, addr);
            }
            unsigned fv[8][4];
            #pragma unroll
            for (int nv = 0; nv < 8; nv++) {
                int tv = nv >> 2;
                int cw = (nv & 3) * 2 + v_csel;
                int key = kc2 * 16 + v_roff;
                unsigned addr = vbb +
                    (tv * 8192 + key * 64 + ((cw ^ l7) << 3)) * 2;
                ldsm4t(fv[nv], addr);
            }
            #pragma unroll
            for (int nt = 0; nt < 16; nt++)
                mma_f16(oc[nt], fa[0], fa[1], fa[2], fa[3],
                        fv[nt >> 1][(nt & 1) * 2], fv[nt >> 1][(nt & 1) * 2 + 1]);
        }
    }

    float inv0 = 1.f / l0, inv1 = 1.f / l1;
    __half* ob  = out + (size_t)(b * SEQ + qr0) * D_MODEL + h * HD;
    __half* ob1 = ob + 8 * D_MODEL;
    #pragma unroll
    for (int nt = 0; nt < 16; nt++) {
        *(__half2*)&ob[nt * 8 + 2 * c] =
            __floats2half2_rn(oc[nt][0] * inv0, oc[nt][1] * inv0);
        *(__half2*)&ob1[nt * 8 + 2 * c] =
            __floats2half2_rn(oc[nt][2] * inv1, oc[nt][3] * inv1);
    }
}

// ============================ launch ============================
extern "C" void kernel_launch(void* const* d_in, const int* in_sizes, int n_in,
                              void* d_out, int out_size)
{
    const float* x      = (const float*)d_in[0];
    const float* ln1_w  = (const float*)d_in[1];
    const float* ln1_b  = (const float*)d_in[2];
    const float* Wqkv   = (const float*)d_in[3];
    const float* bqkv   = (const float*)d_in[4];
    const float* Wo     = (const float*)d_in[5];
    const float* bo     = (const float*)d_in[6];
    const float* ln2_w  = (const float*)d_in[7];
    const float* ln2_b  = (const float*)d_in[8];
    const float* W1     = (const float*)d_in[9];
    const float* b1     = (const float*)d_in[10];
    const float* W2     = (const float*)d_in[11];
    const float* b2     = (const float*)d_in[12];
    const float* slopes = (const float*)d_in[13];
    float* out = (float*)d_out;

    __half *h, *qkv, *attn, *mlp, *wh;
    cudaGetSymbolAddress((void**)&h,    g_h);
    cudaGetSymbolAddress((void**)&qkv,  g_qkv);
    cudaGetSymbolAddress((void**)&attn, g_attn);
    cudaGetSymbolAddress((void**)&mlp,  g_mlp);
    cudaGetSymbolAddress((void**)&wh,   g_wh);

    cudaFuncSetAttribute(attn_kernel,
                         cudaFuncAttributeMaxDynamicSharedMemorySize, ATT_SMEM);
    cudaFuncSetAttribute(gemm_kernel<0>,
                         cudaFuncAttributeMaxDynamicSharedMemorySize, GEMM_SMEM);
    cudaFuncSetAttribute(gemm_kernel<1>,
                         cudaFuncAttributeMaxDynamicSharedMemorySize, GEMM_SMEM);
    cudaFuncSetAttribute(gemm_kernel<2>,
                         cudaFuncAttributeMaxDynamicSharedMemorySize, GEMM_SMEM);

    // 0. convert weights to half (four separate launches — protected invariant)
    {
        int n8;
        n8 = 3 * D_MODEL * D_MODEL / 8;
        to_half_kernel<<<(n8 + 255) / 256, 256>>>((const float4*)Wqkv,
            (uint4*)(wh + WQKV_OFF), n8);
        n8 = D_MODEL * D_MODEL / 8;
        to_half_kernel<<<(n8 + 255) / 256, 256>>>((const float4*)Wo,
            (uint4*)(wh + WO_OFF), n8);
        n8 = D_FF * D_MODEL / 8;
        to_half_kernel<<<(n8 + 255) / 256, 256>>>((const float4*)W1,
            (uint4*)(wh + W1_OFF), n8);
        n8 = D_MODEL * D_FF / 8;
        to_half_kernel<<<(n8 + 255) / 256, 256>>>((const float4*)W2,
            (uint4*)(wh + W2_OFF), n8);
    }

    // 1. LN1 -> half
    ln_kernel<<<ROWS, 256>>>(x, ln1_w, ln1_b, h);
    // 2. QKV GEMM -> half
    gemm_kernel<0><<<dim3(QKV_N / GBN, ROWS / GBM), 256, GEMM_SMEM>>>(
        h, wh + WQKV_OFF, bqkv, nullptr, qkv, ROWS, QKV_N, D_MODEL);
    // 3. Flash attention with ALiBi (fp16 mma, KV tile 128) -> half
    attn_kernel<<<dim3(SEQ / 128, NH, BATCH), 256, ATT_SMEM>>>(qkv, slopes, attn);
    // 4. O projection + residual (x) -> d_out fp32
    gemm_kernel<1><<<dim3(D_MODEL / GBN, ROWS / GBM), 256, GEMM_SMEM>>>(
        attn, wh + WO_OFF, bo, x, out, ROWS, D_MODEL, D_MODEL);
    // 5. LN2 -> half
    ln_kernel<<<ROWS, 256>>>(out, ln2_w, ln2_b, h);
    // 6. MLP up + GELU -> half
    gemm_kernel<2><<<dim3(D_FF / GBN, ROWS / GBM), 256, GEMM_SMEM>>>(
        h, wh + W1_OFF, b1, nullptr, mlp, ROWS, D_FF, D_MODEL);
    // 7. MLP down + residual (x1 in d_out) -> d_out fp32 final
    gemm_kernel<1><<<dim3(D_MODEL / GBN, ROWS / GBM), 256, GEMM_SMEM>>>(
        mlp, wh + W2_OFF, b2, out, out, ROWS, D_MODEL, D_FF);
}